// round 1
// baseline (speedup 1.0000x reference)
#include <cuda_runtime.h>
#include <cstdint>

// Problem constants (fixed shapes from reference)
#define BB   16
#define NN   2000
#define CC   20
#define NPAD 2048          // next pow2 >= NN for bitonic sort
#define NW   32            // ceil(NN/64) 64-bit mask words per row
#define WIMG 602.0f
#define MINB 5.0f
#define BCT  0.01f
#define CTHR 0.001f
#define IOUT 0.2f
#define MAXWH 4096.0f

// ---------------- static device scratch (no allocations allowed) ----------------
__device__ unsigned long long g_keys[BB][NPAD];      // sort keys
__device__ float4             g_sbox[BB][NN];        // sorted boxes + class offset (for IoU)
__device__ float4             g_obox[BB][NN];        // sorted boxes, original clipped (for output)
__device__ float              g_sarea[BB][NN];       // area of offset box (matches ref float order)
__device__ float              g_sscore[BB][NN];
__device__ int                g_scls[BB][NN];
__device__ int                g_svalid[BB][NN];
__device__ unsigned long long g_mask[BB][NN][NW];    // suppression bitmask rows (8.2 MB)
__device__ unsigned long long g_removed[BB][NW];

__device__ __forceinline__ float neg_inf_f() { return __uint_as_float(0xff800000u); }

// ---------------- K1: per-proposal score/valid -> sort key ----------------
__global__ void k1_keys(const float* __restrict__ prop,
                        const float* __restrict__ preds,
                        const float* __restrict__ bscp) {
    int t = blockIdx.x * blockDim.x + threadIdx.x;
    if (t >= BB * NPAD) return;
    int b = t / NPAD, n = t % NPAD;
    if (n >= NN) { g_keys[b][n] = 0ull; return; }

    const float* p = prop + ((size_t)b * NN + n) * 4;
    float x1 = fminf(fmaxf(p[0], 0.f), WIMG);
    float y1 = fminf(fmaxf(p[1], 0.f), WIMG);
    float x2 = fminf(fmaxf(p[2], 0.f), WIMG);
    float y2 = fminf(fmaxf(p[3], 0.f), WIMG);

    const float* pd = preds + ((size_t)b * NN + n) * CC;
    float best = pd[0];
#pragma unroll
    for (int c = 1; c < CC; c++) { float v = pd[c]; if (v > best) best = v; }

    float bsc = bscp[b * NN + n];
    float s = bsc * best;
    bool valid = (bsc > BCT) && ((x2 - x1) >= MINB) && ((y2 - y1) >= MINB) && (s > CTHR);

    float sv = valid ? s : neg_inf_f();
    unsigned u = __float_as_uint(sv);
    u = (u & 0x80000000u) ? ~u : (u | 0x80000000u);     // monotone float->uint map
    // descending score, ascending original index on ties (stable like jnp.argsort)
    g_keys[b][n] = ((unsigned long long)u << 32) | (unsigned)(~(unsigned)n);
}

// ---------------- K2: bitonic sort (descending) of 2048 keys per image ----------------
__global__ void k2_sort() {
    __shared__ unsigned long long s[NPAD];
    int b = blockIdx.x;
    int tid = threadIdx.x;                 // 1024 threads
    s[tid]        = g_keys[b][tid];
    s[tid + 1024] = g_keys[b][tid + 1024];
    __syncthreads();
    for (int k = 2; k <= NPAD; k <<= 1) {
        for (int j = k >> 1; j > 0; j >>= 1) {
#pragma unroll
            for (int off = 0; off < 2; off++) {
                int i = tid + off * 1024;
                int ixj = i ^ j;
                if (ixj > i) {
                    unsigned long long a = s[i], c = s[ixj];
                    bool up = ((i & k) == 0);
                    bool sw = up ? (a < c) : (a > c);   // descending overall
                    if (sw) { s[i] = c; s[ixj] = a; }
                }
            }
            __syncthreads();
        }
    }
    g_keys[b][tid]        = s[tid];
    g_keys[b][tid + 1024] = s[tid + 1024];
}

// ---------------- K3: gather sorted per-proposal data ----------------
__global__ void k3_gather(const float* __restrict__ prop,
                          const float* __restrict__ preds,
                          const float* __restrict__ bscp) {
    int t = blockIdx.x * blockDim.x + threadIdx.x;
    if (t >= BB * NN) return;
    int b = t / NN, ppos = t % NN;
    unsigned long long key = g_keys[b][ppos];
    int n = (int)(~(unsigned)key);                      // original index

    const float* p = prop + ((size_t)b * NN + n) * 4;
    float x1 = fminf(fmaxf(p[0], 0.f), WIMG);
    float y1 = fminf(fmaxf(p[1], 0.f), WIMG);
    float x2 = fminf(fmaxf(p[2], 0.f), WIMG);
    float y2 = fminf(fmaxf(p[3], 0.f), WIMG);

    const float* pd = preds + ((size_t)b * NN + n) * CC;
    float best = pd[0]; int cid = 0;
#pragma unroll
    for (int c = 1; c < CC; c++) { float v = pd[c]; if (v > best) { best = v; cid = c; } }

    float bsc = bscp[b * NN + n];
    float s = bsc * best;
    bool valid = (bsc > BCT) && ((x2 - x1) >= MINB) && ((y2 - y1) >= MINB) && (s > CTHR);

    // class-offset boxes, float add exactly as reference (rounding included)
    float off = (float)cid * MAXWH;
    float ox1 = x1 + off, oy1 = y1 + off, ox2 = x2 + off, oy2 = y2 + off;

    g_sbox[b][ppos]  = make_float4(ox1, oy1, ox2, oy2);
    g_obox[b][ppos]  = make_float4(x1, y1, x2, y2);
    g_sarea[b][ppos] = fmaxf(ox2 - ox1, 0.f) * fmaxf(oy2 - oy1, 0.f);  // ref computes area post-offset
    g_sscore[b][ppos] = s;
    g_scls[b][ppos]   = cid;
    g_svalid[b][ppos] = valid ? 1 : 0;
}

// ---------------- K4: pairwise IoU suppression mask (torchvision-style) ----------------
__global__ void k4_mask() {
    int b  = blockIdx.z;
    int rb = blockIdx.y;       // row block (i)
    int cb = blockIdx.x;       // col block (j), 64 cols
    __shared__ float4 cbx[64];
    __shared__ float  car[64];
    int j = cb * 64 + threadIdx.x;
    if (j < NN) { cbx[threadIdx.x] = g_sbox[b][j]; car[threadIdx.x] = g_sarea[b][j]; }
    else        { cbx[threadIdx.x] = make_float4(0.f,0.f,0.f,0.f); car[threadIdx.x] = 0.f; }
    __syncthreads();

    int i = rb * 64 + threadIdx.x;
    if (i >= NN) return;
    float4 bi = g_sbox[b][i];
    float  ai = g_sarea[b][i];
    unsigned long long m = 0ull;
    int jmax = min(64, NN - cb * 64);
#pragma unroll 4
    for (int jj = 0; jj < jmax; jj++) {
        int jg = cb * 64 + jj;
        if (jg <= i) continue;                          // only suppress later (lower-score) boxes
        float4 bj = cbx[jj];
        float lx = fmaxf(bi.x, bj.x), ly = fmaxf(bi.y, bj.y);
        float rx = fminf(bi.z, bj.z), ry = fminf(bi.w, bj.w);
        float w = fmaxf(rx - lx, 0.f), h = fmaxf(ry - ly, 0.f);
        float inter = w * h;
        float uni = ai + car[jj] - inter;
        float iou = __fdiv_rn(inter, fmaxf(uni, 1e-9f));  // IEEE div even under fast-math
        if (iou > IOUT) m |= (1ull << jj);
    }
    g_mask[b][i][cb] = m;
}

// ---------------- K5: serial greedy scan, one warp per image ----------------
__global__ void k5_reduce() {
    int b = blockIdx.x;
    int lane = threadIdx.x;                            // 32 lanes = 32 mask words
    unsigned long long removed = 0ull;
    unsigned long long nxt_row = g_mask[b][0][lane];
    int nxt_valid = g_svalid[b][0];
    for (int i = 0; i < NN; i++) {
        unsigned long long row = nxt_row;
        int vld = nxt_valid;
        if (i + 1 < NN) {                              // prefetch next row
            nxt_row   = g_mask[b][i + 1][lane];
            nxt_valid = g_svalid[b][i + 1];
        }
        unsigned long long w = __shfl_sync(0xffffffffu, removed, i >> 6);
        bool alive = vld && !((w >> (i & 63)) & 1ull);
        if (alive) removed |= row;
    }
    g_removed[b][lane] = removed;
}

// ---------------- K6: write [B,N,6] output ----------------
__global__ void k6_out(float* __restrict__ out) {
    int t = blockIdx.x * blockDim.x + threadIdx.x;
    if (t >= BB * NN) return;
    int b = t / NN, p = t % NN;
    unsigned long long w = g_removed[b][p >> 6];
    bool rem = (w >> (p & 63)) & 1ull;
    bool keep = g_svalid[b][p] && !rem;
    float* o = out + ((size_t)b * NN + p) * 6;
    if (keep) {
        float4 bx = g_obox[b][p];
        o[0] = bx.x; o[1] = bx.y; o[2] = bx.z; o[3] = bx.w;
        o[4] = g_sscore[b][p];
        o[5] = (float)g_scls[b][p];
    } else {
        o[0] = 0.f; o[1] = 0.f; o[2] = 0.f; o[3] = 0.f; o[4] = 0.f; o[5] = 0.f;
    }
}

extern "C" void kernel_launch(void* const* d_in, const int* in_sizes, int n_in,
                              void* d_out, int out_size) {
    const float* prop  = (const float*)d_in[0];   // [16,2000,4]
    const float* preds = (const float*)d_in[1];   // [16,2000,20]
    const float* bsc   = (const float*)d_in[2];   // [16,2000]
    float* out = (float*)d_out;                   // [16,2000,6]

    (void)in_sizes; (void)n_in; (void)out_size;

    int tot1 = BB * NPAD;
    k1_keys<<<(tot1 + 255) / 256, 256>>>(prop, preds, bsc);
    k2_sort<<<BB, 1024>>>();
    int tot2 = BB * NN;
    k3_gather<<<(tot2 + 255) / 256, 256>>>(prop, preds, bsc);
    dim3 mg((NN + 63) / 64, (NN + 63) / 64, BB);
    k4_mask<<<mg, 64>>>();
    k5_reduce<<<BB, 32>>>();
    k6_out<<<(tot2 + 255) / 256, 256>>>(out);
}